// round 3
// baseline (speedup 1.0000x reference)
#include <cuda_runtime.h>
#include <math.h>

#define N_NODES 50000
#define N_EDGES 800000
#define D 64

typedef unsigned long long ull;

// ------------------------- device scratch (no allocs allowed) ---------------
// NOTE: these are referenced ONLY from device code. Passing a __device__
// symbol from host code as a kernel arg passes the HOST shadow address,
// which GB300's ATS dereferences silently (reads zeros) — that was the
// round-1/2 bug.
__device__ float g_wh[N_NODES * D];        // per-node transformed features
__device__ float g_agg[N_NODES * D];       // aggregated messages
__device__ int   g_rowptr[N_NODES + 1];    // CSR row pointers (by dst)
__device__ int   g_cnt[N_NODES];           // in-degree counts
__device__ int   g_cursor[N_NODES];        // fill cursors
__device__ int   g_srcsorted[N_EDGES];     // src ids grouped by dst

// ------------------------- f32x2 helpers ------------------------------------
__device__ __forceinline__ ull ffma2(ull a, ull b, ull c) {
    ull d;
    asm("fma.rn.f32x2 %0, %1, %2, %3;" : "=l"(d) : "l"(a), "l"(b), "l"(c));
    return d;
}
__device__ __forceinline__ ull pack2f(float x, float y) {
    ull r;
    asm("mov.b64 %0, {%1, %2};" : "=l"(r) : "f"(x), "f"(y));
    return r;
}
__device__ __forceinline__ float2 unpack2(ull v) {
    float2 f;
    asm("mov.b64 {%0, %1}, %2;" : "=f"(f.x), "=f"(f.y) : "l"(v));
    return f;
}
__device__ __forceinline__ float sigmoidf_(float x) {
    return 1.0f / (1.0f + __expf(-x));
}

// ------------------------- CSR build ----------------------------------------
__global__ void zero_cnt_kernel() {
    int i = blockIdx.x * blockDim.x + threadIdx.x;
    if (i < N_NODES) g_cnt[i] = 0;
}

__global__ void count_kernel(const int* __restrict__ dst) {
    int e = blockIdx.x * blockDim.x + threadIdx.x;
    if (e < N_EDGES) atomicAdd(&g_cnt[dst[e]], 1);
}

// single-block scan: builds g_rowptr (exclusive, size N+1) and g_cursor
__global__ void scan_kernel() {
    __shared__ int wsum[32];
    __shared__ int carry_s;
    int t = threadIdx.x, lane = t & 31, w = t >> 5;
    if (t == 0) { g_rowptr[0] = 0; carry_s = 0; }
    __syncthreads();
    for (int base = 0; base < N_NODES; base += 1024) {
        int i = base + t;
        int v = (i < N_NODES) ? g_cnt[i] : 0;
        int x = v;
#pragma unroll
        for (int off = 1; off < 32; off <<= 1) {
            int y = __shfl_up_sync(0xffffffffu, x, off);
            if (lane >= off) x += y;
        }
        if (lane == 31) wsum[w] = x;
        __syncthreads();
        if (w == 0) {
            int s = wsum[lane];
            int xs = s;
#pragma unroll
            for (int off = 1; off < 32; off <<= 1) {
                int y = __shfl_up_sync(0xffffffffu, xs, off);
                if (lane >= off) xs += y;
            }
            wsum[lane] = xs - s;   // exclusive warp offsets
        }
        __syncthreads();
        int incl = x + wsum[w];
        int carry = carry_s;
        if (i < N_NODES) {
            g_rowptr[i + 1] = carry + incl;
            g_cursor[i]     = carry + incl - v;
        }
        __syncthreads();
        if (t == 1023) carry_s = carry + incl;
        __syncthreads();
    }
}

__global__ void fill_kernel(const int* __restrict__ src, const int* __restrict__ dst) {
    int e = blockIdx.x * blockDim.x + threadIdx.x;
    if (e < N_EDGES) {
        int d = dst[e];
        int pos = atomicAdd(&g_cursor[d], 1);
        g_srcsorted[pos] = src[e];
    }
}

// ------------------------- wh = h @ W^T + b ----------------------------------
// CTA: 64 rows, 256 threads; thread = (row r, 16-col block), f32x2 FMA
__global__ void __launch_bounds__(256) gemm1_kernel(
    const float* __restrict__ hin, const float* __restrict__ W,
    const float* __restrict__ b) {
    extern __shared__ float sm[];
    float*  Wt    = sm;                               // [64][64] : Wt[k][j] = W[j][k]
    float2* Xd    = (float2*)(sm + 64 * 64);          // [64][65] duplicated pairs
    float*  stage = sm + 64 * 64 + 64 * 65 * 2;       // [64][65]

    int t = threadIdx.x;
    int row0 = blockIdx.x * 64;

    // stage W coalesced: stage[j][k] = W[j*64+k]
    for (int i = t; i < 64 * 64; i += 256) {
        int j = i >> 6, k = i & 63;
        stage[j * 65 + k] = W[i];
    }
    // X tile, duplicated for f32x2 broadcast operand
    for (int i = t; i < 64 * 64; i += 256) {
        int r = i >> 6, k = i & 63;
        int g = row0 + r;
        float v = (g < N_NODES) ? hin[(size_t)g * 64 + k] : 0.0f;
        Xd[r * 65 + k] = make_float2(v, v);
    }
    __syncthreads();
    // conflict-free transpose: read stride-65, write contiguous
    for (int i = t; i < 64 * 64; i += 256) {
        int k = i >> 6, j = i & 63;
        Wt[k * 64 + j] = stage[j * 65 + k];
    }
    __syncthreads();

    int r  = t >> 2;
    int cb = (t & 3) << 4;    // 16 columns per thread
    ull acc[8];
#pragma unroll
    for (int p = 0; p < 8; p++) {
        float2 bb = *(const float2*)&b[cb + 2 * p];
        acc[p] = pack2f(bb.x, bb.y);
    }
#pragma unroll 8
    for (int k = 0; k < 64; k++) {
        ull x2 = *(const ull*)&Xd[r * 65 + k];
        const ull* wr = (const ull*)&Wt[k * 64 + cb];
#pragma unroll
        for (int p = 0; p < 8; p++) acc[p] = ffma2(x2, wr[p], acc[p]);
    }
    int g = row0 + r;
    if (g < N_NODES) {
        float2* o = (float2*)&g_wh[(size_t)g * 64 + cb];
#pragma unroll
        for (int p = 0; p < 8; p++) o[p] = unpack2(acc[p]);
    }
}

// ------------------------- aggregation: one warp per dst node ---------------
__global__ void __launch_bounds__(256) agg_kernel() {
    int gw = (blockIdx.x * blockDim.x + threadIdx.x) >> 5;
    if (gw >= N_NODES) return;
    int lane = threadIdx.x & 31;
    int p = g_rowptr[gw];
    int e = g_rowptr[gw + 1];
    float ax = 0.0f, ay = 0.0f;
    for (; p + 2 <= e; p += 2) {
        int s0 = g_srcsorted[p];
        int s1 = g_srcsorted[p + 1];
        float2 m0 = *(const float2*)&g_wh[(size_t)s0 * 64 + lane * 2];
        float2 m1 = *(const float2*)&g_wh[(size_t)s1 * 64 + lane * 2];
        ax += m0.x; ay += m0.y;
        ax += m1.x; ay += m1.y;
    }
    if (p < e) {
        int s0 = g_srcsorted[p];
        float2 m0 = *(const float2*)&g_wh[(size_t)s0 * 64 + lane * 2];
        ax += m0.x; ay += m0.y;
    }
    *(float2*)&g_agg[(size_t)gw * 64 + lane * 2] = make_float2(ax, ay);
}

// ------------------------- fused GRU cell ------------------------------------
// CTA: 32 rows, 256 threads; thread = (row, 8-dim block) -> 24 f32x2 accumulators
// Reads aggregated messages from g_agg DIRECTLY (device symbol, not a param).
#define GRU_ROWS 32
__global__ void __launch_bounds__(256) gru_kernel(
    const float* __restrict__ hin,
    const float* __restrict__ Wih, const float* __restrict__ Whh,
    const float* __restrict__ bih, const float* __restrict__ bhh,
    float* __restrict__ hout) {
    extern __shared__ float sm[];
    float*  WihT  = sm;                        // [64][192]
    float*  WhhT  = WihT + 64 * 192;           // [64][192]
    float*  stage = WhhT + 64 * 192;           // [192][65]
    float2* Ad    = (float2*)(stage + 192 * 65);   // [32][65] duplicated
    float2* Hd    = Ad + 32 * 65;                  // [32][65] duplicated
    float*  sbih  = (float*)(Hd + 32 * 65);    // [192]
    float*  sbhh  = sbih + 192;                // [192]

    int t = threadIdx.x;
    int row0 = blockIdx.x * GRU_ROWS;

    if (t < 192) { sbih[t] = bih[t]; sbhh[t] = bhh[t]; }
    for (int i = t; i < GRU_ROWS * 64; i += 256) {
        int r = i >> 6, k = i & 63;
        int g = row0 + r;
        float av = (g < N_NODES) ? g_agg[(size_t)g * 64 + k] : 0.0f;
        float hv = (g < N_NODES) ? hin[(size_t)g * 64 + k] : 0.0f;
        Ad[r * 65 + k] = make_float2(av, av);
        Hd[r * 65 + k] = make_float2(hv, hv);
    }
    // Wih transpose via padded staging (conflict-free both phases)
    for (int i = t; i < 192 * 64; i += 256) {
        int j = i >> 6, k = i & 63;
        stage[j * 65 + k] = Wih[i];
    }
    __syncthreads();
    for (int i = t; i < 192 * 64; i += 256) {
        int k = i / 192, j = i % 192;
        WihT[k * 192 + j] = stage[j * 65 + k];
    }
    __syncthreads();
    for (int i = t; i < 192 * 64; i += 256) {
        int j = i >> 6, k = i & 63;
        stage[j * 65 + k] = Whh[i];
    }
    __syncthreads();
    for (int i = t; i < 192 * 64; i += 256) {
        int k = i / 192, j = i % 192;
        WhhT[k * 192 + j] = stage[j * 65 + k];
    }
    __syncthreads();

    int r  = t >> 3;
    int db = (t & 7) << 3;   // 8 output dims -> 4 f32x2 pairs, 3 gates, gi+gh

    ull A[3][4], B[3][4];
#pragma unroll
    for (int g = 0; g < 3; g++)
#pragma unroll
        for (int p = 0; p < 4; p++) { A[g][p] = 0ull; B[g][p] = 0ull; }

#pragma unroll 4
    for (int k = 0; k < 64; k++) {
        ull a2 = *(const ull*)&Ad[r * 65 + k];
        ull h2 = *(const ull*)&Hd[r * 65 + k];
        const float* wi = &WihT[k * 192 + db];
        const float* wh = &WhhT[k * 192 + db];
#pragma unroll
        for (int g = 0; g < 3; g++) {
#pragma unroll
            for (int p = 0; p < 4; p++) {
                A[g][p] = ffma2(a2, *(const ull*)&wi[g * 64 + 2 * p], A[g][p]);
                B[g][p] = ffma2(h2, *(const ull*)&wh[g * 64 + 2 * p], B[g][p]);
            }
        }
    }

    int gnode = row0 + r;
    if (gnode < N_NODES) {
#pragma unroll
        for (int p = 0; p < 4; p++) {
            int d = db + 2 * p;
            float2 ir = unpack2(A[0][p]);
            float2 iz = unpack2(A[1][p]);
            float2 in_ = unpack2(A[2][p]);
            float2 hr = unpack2(B[0][p]);
            float2 hz = unpack2(B[1][p]);
            float2 hn = unpack2(B[2][p]);

            float r0 = sigmoidf_(ir.x + sbih[d]     + hr.x + sbhh[d]);
            float r1 = sigmoidf_(ir.y + sbih[d + 1] + hr.y + sbhh[d + 1]);
            float z0 = sigmoidf_(iz.x + sbih[64 + d]     + hz.x + sbhh[64 + d]);
            float z1 = sigmoidf_(iz.y + sbih[64 + d + 1] + hz.y + sbhh[64 + d + 1]);
            float n0 = tanhf(in_.x + sbih[128 + d]     + r0 * (hn.x + sbhh[128 + d]));
            float n1 = tanhf(in_.y + sbih[128 + d + 1] + r1 * (hn.y + sbhh[128 + d + 1]));

            float hold0 = Hd[r * 65 + d].x;
            float hold1 = Hd[r * 65 + d + 1].x;
            float o0 = (1.0f - z0) * n0 + z0 * hold0;
            float o1 = (1.0f - z1) * n1 + z1 * hold1;
            *(float2*)&hout[(size_t)gnode * 64 + d] = make_float2(o0, o1);
        }
    }
}

// ------------------------- launch --------------------------------------------
extern "C" void kernel_launch(void* const* d_in, const int* in_sizes, int n_in,
                              void* d_out, int out_size) {
    // Size-based input mapping (empirically identical to positional order).
    const float *node_in = 0, *W = 0, *b = 0, *Wih = 0, *Whh = 0, *bih = 0, *bhh = 0;
    const int *src = 0, *dst = 0;
    int n12288 = 0, n192 = 0, n800k = 0;
    for (int i = 0; i < n_in; i++) {
        switch (in_sizes[i]) {
            case N_NODES * D: node_in = (const float*)d_in[i]; break;
            case D * D:       W = (const float*)d_in[i]; break;
            case D:           b = (const float*)d_in[i]; break;
            case 3 * D * D:
                if (n12288++ == 0) Wih = (const float*)d_in[i];
                else               Whh = (const float*)d_in[i];
                break;
            case 3 * D:
                if (n192++ == 0) bih = (const float*)d_in[i];
                else             bhh = (const float*)d_in[i];
                break;
            case N_EDGES:
                if (n800k++ == 0) src = (const int*)d_in[i];
                else              dst = (const int*)d_in[i];
                break;
            default: break;
        }
    }
    float* h = (float*)d_out;

    const int GEMM1_SMEM = (64 * 64 + 64 * 65 * 2 + 64 * 65) * 4;                 // 66304 B
    const int GRU_SMEM   = (64 * 192 * 2 + 192 * 65 + 32 * 65 * 2 * 2 + 384) * 4; // 183040 B
    cudaFuncSetAttribute(gemm1_kernel, cudaFuncAttributeMaxDynamicSharedMemorySize, GEMM1_SMEM);
    cudaFuncSetAttribute(gru_kernel,   cudaFuncAttributeMaxDynamicSharedMemorySize, GRU_SMEM);

    // CSR build (once per launch, reused across 3 steps)
    zero_cnt_kernel<<<(N_NODES + 255) / 256, 256>>>();
    count_kernel<<<(N_EDGES + 255) / 256, 256>>>(dst);
    scan_kernel<<<1, 1024>>>();
    fill_kernel<<<(N_EDGES + 255) / 256, 256>>>(src, dst);

    const int gemm1_grid = (N_NODES + 63) / 64;
    const int agg_grid   = (N_NODES * 32 + 255) / 256;
    const int gru_grid   = (N_NODES + GRU_ROWS - 1) / GRU_ROWS;

    for (int step = 0; step < 3; step++) {
        const float* hcur = (step == 0) ? node_in : h;
        gemm1_kernel<<<gemm1_grid, 256, GEMM1_SMEM>>>(hcur, W, b);
        agg_kernel<<<agg_grid, 256>>>();
        gru_kernel<<<gru_grid, 256, GRU_SMEM>>>(hcur, Wih, Whh, bih, bhh, h);
    }
}

// round 4
// speedup vs baseline: 3.3671x; 3.3671x over previous
#include <cuda_runtime.h>
#include <math.h>

#define N_NODES 50000
#define N_EDGES 800000
#define D 64

typedef unsigned long long ull;

// ------------------------- device scratch (no allocs allowed) ---------------
// Referenced ONLY from device code (host-side use of a __device__ symbol
// passes the host shadow address, which ATS dereferences silently - R1/2 bug).
__device__ float g_wh[N_NODES * D];        // per-node transformed features
__device__ float g_agg[N_NODES * D];       // aggregated messages
__device__ int   g_rowptr[N_NODES + 1];    // CSR row pointers (by dst)
__device__ int   g_cnt[N_NODES];           // in-degree counts
__device__ int   g_cursor[N_NODES];        // fill cursors
__device__ int   g_srcsorted[N_EDGES];     // src ids grouped by dst
// pre-transposed weights / pre-combined biases (built once per launch)
__device__ float g_wihT[64 * 192];         // g_wihT[k*192+j] = Wih[j*64+k]
__device__ float g_whhT[64 * 192];         // g_whhT[k*192+j] = Whh[j*64+k]
__device__ float g_wT[64 * 64];            // g_wT[k*64+j]    = W[j*64+k]
__device__ float g_brz[128];               // bih[d]+bhh[d] for r,z gates
__device__ float g_bni[64];                // bih[128+d]
__device__ float g_bnh[64];                // bhh[128+d]

// ------------------------- f32x2 helpers ------------------------------------
__device__ __forceinline__ ull ffma2(ull a, ull b, ull c) {
    ull d;
    asm("fma.rn.f32x2 %0, %1, %2, %3;" : "=l"(d) : "l"(a), "l"(b), "l"(c));
    return d;
}
__device__ __forceinline__ ull pack2f(float x, float y) {
    ull r;
    asm("mov.b64 %0, {%1, %2};" : "=l"(r) : "f"(x), "f"(y));
    return r;
}
__device__ __forceinline__ float2 unpack2(ull v) {
    float2 f;
    asm("mov.b64 {%0, %1}, %2;" : "=f"(f.x), "=f"(f.y) : "l"(v));
    return f;
}
__device__ __forceinline__ float sigmoidf_(float x) {
    return 1.0f / (1.0f + __expf(-x));
}

// ------------------------- prep: transpose weights, combine biases ----------
__global__ void prep_kernel(const float* __restrict__ W,
                            const float* __restrict__ Wih,
                            const float* __restrict__ Whh,
                            const float* __restrict__ bih,
                            const float* __restrict__ bhh) {
    int i = blockIdx.x * blockDim.x + threadIdx.x;
    if (i < 12288) {
        int k = i / 192, j = i % 192;
        g_wihT[i] = Wih[j * 64 + k];
    } else if (i < 24576) {
        int e = i - 12288; int k = e / 192, j = e % 192;
        g_whhT[e] = Whh[j * 64 + k];
    } else if (i < 28672) {
        int e = i - 24576; int k = e / 64, j = e % 64;
        g_wT[e] = W[j * 64 + k];
    } else if (i < 28800) {
        int d = i - 28672;
        g_brz[d] = bih[d] + bhh[d];
    } else if (i < 28864) {
        int d = i - 28800;
        g_bni[d] = bih[128 + d];
    } else if (i < 28928) {
        int d = i - 28864;
        g_bnh[d] = bhh[128 + d];
    }
}

// ------------------------- CSR build ----------------------------------------
__global__ void zero_cnt_kernel() {
    int i = blockIdx.x * blockDim.x + threadIdx.x;
    if (i < N_NODES) g_cnt[i] = 0;
}

__global__ void count_kernel(const int* __restrict__ dst) {
    int e = blockIdx.x * blockDim.x + threadIdx.x;
    if (e < N_EDGES) atomicAdd(&g_cnt[dst[e]], 1);
}

__global__ void scan_kernel() {
    __shared__ int wsum[32];
    __shared__ int carry_s;
    int t = threadIdx.x, lane = t & 31, w = t >> 5;
    if (t == 0) { g_rowptr[0] = 0; carry_s = 0; }
    __syncthreads();
    for (int base = 0; base < N_NODES; base += 1024) {
        int i = base + t;
        int v = (i < N_NODES) ? g_cnt[i] : 0;
        int x = v;
#pragma unroll
        for (int off = 1; off < 32; off <<= 1) {
            int y = __shfl_up_sync(0xffffffffu, x, off);
            if (lane >= off) x += y;
        }
        if (lane == 31) wsum[w] = x;
        __syncthreads();
        if (w == 0) {
            int s = wsum[lane];
            int xs = s;
#pragma unroll
            for (int off = 1; off < 32; off <<= 1) {
                int y = __shfl_up_sync(0xffffffffu, xs, off);
                if (lane >= off) xs += y;
            }
            wsum[lane] = xs - s;
        }
        __syncthreads();
        int incl = x + wsum[w];
        int carry = carry_s;
        if (i < N_NODES) {
            g_rowptr[i + 1] = carry + incl;
            g_cursor[i]     = carry + incl - v;
        }
        __syncthreads();
        if (t == 1023) carry_s = carry + incl;
        __syncthreads();
    }
}

__global__ void fill_kernel(const int* __restrict__ src, const int* __restrict__ dst) {
    int e = blockIdx.x * blockDim.x + threadIdx.x;
    if (e < N_EDGES) {
        int d = dst[e];
        int pos = atomicAdd(&g_cursor[d], 1);
        g_srcsorted[pos] = src[e];
    }
}

// ------------------------- wh = h @ W^T + b ----------------------------------
// 256 threads, 64 rows/CTA. thread = (rowslot t>>4, dimslot t&15 -> 4 dims),
// R=4 rows per thread; weights loaded once per k, reused across rows.
#define T_STRIDE 68   // tile row stride (16B-aligned, conflict-free broadcast)
__global__ void __launch_bounds__(256) gemm1_kernel(
    const float* __restrict__ hin, const float* __restrict__ b) {
    __shared__ float wTs[64 * 64];       // [k][j]
    __shared__ float Xs[64 * T_STRIDE];  // [row][k]
    __shared__ float sb[64];

    int t = threadIdx.x;
    int row0 = blockIdx.x * 64;

    if (t < 64) sb[t] = b[t];
    for (int i = t; i < 1024; i += 256)
        ((float4*)wTs)[i] = ((const float4*)g_wT)[i];
    for (int i = t; i < 64 * 16; i += 256) {
        int r = i >> 4, c4 = i & 15;
        int g = row0 + r;
        float4 v = (g < N_NODES) ? ((const float4*)hin)[(size_t)g * 16 + c4]
                                 : make_float4(0.f, 0.f, 0.f, 0.f);
        *(float4*)&Xs[r * T_STRIDE + c4 * 4] = v;
    }
    __syncthreads();

    int ds = t & 15;          // dim slot: dims db..db+3
    int rs = t >> 4;          // row slot: rows rs + 16*i
    int db = ds << 2;

    ull acc[4][2];
    {
        ull b0 = pack2f(sb[db], sb[db + 1]);
        ull b1 = pack2f(sb[db + 2], sb[db + 3]);
#pragma unroll
        for (int i = 0; i < 4; i++) { acc[i][0] = b0; acc[i][1] = b1; }
    }

#pragma unroll 8
    for (int k = 0; k < 64; k++) {
        const ull* wr = (const ull*)&wTs[k * 64 + db];
        ull w0 = wr[0], w1 = wr[1];
#pragma unroll
        for (int i = 0; i < 4; i++) {
            float x = Xs[(rs + 16 * i) * T_STRIDE + k];
            ull x2 = pack2f(x, x);
            acc[i][0] = ffma2(x2, w0, acc[i][0]);
            acc[i][1] = ffma2(x2, w1, acc[i][1]);
        }
    }
#pragma unroll
    for (int i = 0; i < 4; i++) {
        int g = row0 + rs + 16 * i;
        if (g < N_NODES) {
            float2 a = unpack2(acc[i][0]);
            float2 c = unpack2(acc[i][1]);
            *(float4*)&g_wh[(size_t)g * 64 + db] = make_float4(a.x, a.y, c.x, c.y);
        }
    }
}

// ------------------------- aggregation: one warp per dst node ---------------
__global__ void __launch_bounds__(256) agg_kernel() {
    int gw = (blockIdx.x * blockDim.x + threadIdx.x) >> 5;
    if (gw >= N_NODES) return;
    int lane = threadIdx.x & 31;
    int p = g_rowptr[gw];
    int e = g_rowptr[gw + 1];
    float ax = 0.0f, ay = 0.0f;
    for (; p + 2 <= e; p += 2) {
        int s0 = g_srcsorted[p];
        int s1 = g_srcsorted[p + 1];
        float2 m0 = *(const float2*)&g_wh[(size_t)s0 * 64 + lane * 2];
        float2 m1 = *(const float2*)&g_wh[(size_t)s1 * 64 + lane * 2];
        ax += m0.x; ay += m0.y;
        ax += m1.x; ay += m1.y;
    }
    if (p < e) {
        int s0 = g_srcsorted[p];
        float2 m0 = *(const float2*)&g_wh[(size_t)s0 * 64 + lane * 2];
        ax += m0.x; ay += m0.y;
    }
    *(float2*)&g_agg[(size_t)gw * 64 + lane * 2] = make_float2(ax, ay);
}

// ------------------------- fused GRU cell ------------------------------------
// 256 threads, 64 rows/CTA. thread = (rowslot t>>4, dimslot t&15 -> 4 dims),
// R=4 rows; 12 weight ulls per k reused across 4 rows. Merged r/z accums
// (i_r+h_r accumulated together - exact reassociation).
__global__ void __launch_bounds__(256) gru_kernel(
    const float* __restrict__ hin, float* __restrict__ hout) {
    extern __shared__ float sm[];
    float* WihT_s = sm;                    // [64][192]
    float* WhhT_s = WihT_s + 64 * 192;     // [64][192]
    float* As     = WhhT_s + 64 * 192;     // [64][T_STRIDE]
    float* Hs     = As + 64 * T_STRIDE;    // [64][T_STRIDE]
    float* sbrz   = Hs + 64 * T_STRIDE;    // [128]
    float* sbni   = sbrz + 128;            // [64]
    float* sbnh   = sbni + 128 - 64;       // [64]  (== sbrz+192)

    int t = threadIdx.x;
    int row0 = blockIdx.x * 64;

    // weights: straight coalesced copy (pre-transposed in prep_kernel)
    for (int i = t; i < 3072; i += 256)
        ((float4*)WihT_s)[i] = ((const float4*)g_wihT)[i];
    for (int i = t; i < 3072; i += 256)
        ((float4*)WhhT_s)[i] = ((const float4*)g_whhT)[i];
    if (t < 128) sbrz[t] = g_brz[t];
    else if (t < 192) sbni[t - 128] = g_bni[t - 128];
    else if (t < 256) sbnh[t - 192] = g_bnh[t - 192];
    for (int i = t; i < 64 * 16; i += 256) {
        int r = i >> 4, c4 = i & 15;
        int g = row0 + r;
        float4 av = (g < N_NODES) ? *(const float4*)&g_agg[(size_t)g * 64 + c4 * 4]
                                  : make_float4(0.f, 0.f, 0.f, 0.f);
        float4 hv = (g < N_NODES) ? *(const float4*)&hin[(size_t)g * 64 + c4 * 4]
                                  : make_float4(0.f, 0.f, 0.f, 0.f);
        *(float4*)&As[r * T_STRIDE + c4 * 4] = av;
        *(float4*)&Hs[r * T_STRIDE + c4 * 4] = hv;
    }
    __syncthreads();

    int ds = t & 15;
    int rs = t >> 4;
    int db = ds << 2;

    // accumulators: [row][pair] ; R = merged r-gate, Z = merged z, Ni/Nh separate
    ull accR[4][2], accZ[4][2], accNi[4][2], accNh[4][2];
#pragma unroll
    for (int i = 0; i < 4; i++)
#pragma unroll
        for (int p = 0; p < 2; p++) {
            accR[i][p] = 0ull; accZ[i][p] = 0ull;
            accNi[i][p] = 0ull; accNh[i][p] = 0ull;
        }

#pragma unroll 4
    for (int k = 0; k < 64; k++) {
        const ull* wiR = (const ull*)&WihT_s[k * 192 + db];
        const ull* wiZ = (const ull*)&WihT_s[k * 192 + 64 + db];
        const ull* wiN = (const ull*)&WihT_s[k * 192 + 128 + db];
        const ull* whR = (const ull*)&WhhT_s[k * 192 + db];
        const ull* whZ = (const ull*)&WhhT_s[k * 192 + 64 + db];
        const ull* whN = (const ull*)&WhhT_s[k * 192 + 128 + db];
        ull wir0 = wiR[0], wir1 = wiR[1];
        ull wiz0 = wiZ[0], wiz1 = wiZ[1];
        ull win0 = wiN[0], win1 = wiN[1];
        ull whr0 = whR[0], whr1 = whR[1];
        ull whz0 = whZ[0], whz1 = whZ[1];
        ull whn0 = whN[0], whn1 = whN[1];
#pragma unroll
        for (int i = 0; i < 4; i++) {
            int r = rs + 16 * i;
            float av = As[r * T_STRIDE + k];
            float hv = Hs[r * T_STRIDE + k];
            ull a2 = pack2f(av, av);
            ull h2 = pack2f(hv, hv);
            accR[i][0] = ffma2(a2, wir0, accR[i][0]);
            accR[i][1] = ffma2(a2, wir1, accR[i][1]);
            accR[i][0] = ffma2(h2, whr0, accR[i][0]);
            accR[i][1] = ffma2(h2, whr1, accR[i][1]);
            accZ[i][0] = ffma2(a2, wiz0, accZ[i][0]);
            accZ[i][1] = ffma2(a2, wiz1, accZ[i][1]);
            accZ[i][0] = ffma2(h2, whz0, accZ[i][0]);
            accZ[i][1] = ffma2(h2, whz1, accZ[i][1]);
            accNi[i][0] = ffma2(a2, win0, accNi[i][0]);
            accNi[i][1] = ffma2(a2, win1, accNi[i][1]);
            accNh[i][0] = ffma2(h2, whn0, accNh[i][0]);
            accNh[i][1] = ffma2(h2, whn1, accNh[i][1]);
        }
    }

#pragma unroll
    for (int i = 0; i < 4; i++) {
        int r = rs + 16 * i;
        int g = row0 + r;
        if (g >= N_NODES) continue;
        float out[4];
#pragma unroll
        for (int p = 0; p < 2; p++) {
            float2 rr = unpack2(accR[i][p]);
            float2 zz = unpack2(accZ[i][p]);
            float2 ni = unpack2(accNi[i][p]);
            float2 nh = unpack2(accNh[i][p]);
            int d = db + 2 * p;
            float r0 = sigmoidf_(rr.x + sbrz[d]);
            float r1 = sigmoidf_(rr.y + sbrz[d + 1]);
            float z0 = sigmoidf_(zz.x + sbrz[64 + d]);
            float z1 = sigmoidf_(zz.y + sbrz[64 + d + 1]);
            float n0 = tanhf(ni.x + sbni[d]     + r0 * (nh.x + sbnh[d]));
            float n1 = tanhf(ni.y + sbni[d + 1] + r1 * (nh.y + sbnh[d + 1]));
            float h0 = Hs[r * T_STRIDE + d];
            float h1 = Hs[r * T_STRIDE + d + 1];
            out[2 * p]     = (1.0f - z0) * n0 + z0 * h0;
            out[2 * p + 1] = (1.0f - z1) * n1 + z1 * h1;
        }
        *(float4*)&hout[(size_t)g * 64 + db] = make_float4(out[0], out[1], out[2], out[3]);
    }
}

// ------------------------- launch --------------------------------------------
extern "C" void kernel_launch(void* const* d_in, const int* in_sizes, int n_in,
                              void* d_out, int out_size) {
    const float *node_in = 0, *W = 0, *b = 0, *Wih = 0, *Whh = 0, *bih = 0, *bhh = 0;
    const int *src = 0, *dst = 0;
    int n12288 = 0, n192 = 0, n800k = 0;
    for (int i = 0; i < n_in; i++) {
        switch (in_sizes[i]) {
            case N_NODES * D: node_in = (const float*)d_in[i]; break;
            case D * D:       W = (const float*)d_in[i]; break;
            case D:           b = (const float*)d_in[i]; break;
            case 3 * D * D:
                if (n12288++ == 0) Wih = (const float*)d_in[i];
                else               Whh = (const float*)d_in[i];
                break;
            case 3 * D:
                if (n192++ == 0) bih = (const float*)d_in[i];
                else             bhh = (const float*)d_in[i];
                break;
            case N_EDGES:
                if (n800k++ == 0) src = (const int*)d_in[i];
                else              dst = (const int*)d_in[i];
                break;
            default: break;
        }
    }
    float* h = (float*)d_out;

    // GRU dynamic smem: 2*12288 + 2*64*68 + 256 floats = 134,144 B
    const int GRU_SMEM = (2 * 12288 + 2 * 64 * T_STRIDE + 256) * 4;
    cudaFuncSetAttribute(gru_kernel, cudaFuncAttributeMaxDynamicSharedMemorySize, GRU_SMEM);

    // one-time prep: weight transposes + combined biases + CSR
    prep_kernel<<<(28928 + 255) / 256, 256>>>(W, Wih, Whh, bih, bhh);
    zero_cnt_kernel<<<(N_NODES + 255) / 256, 256>>>();
    count_kernel<<<(N_EDGES + 255) / 256, 256>>>(dst);
    scan_kernel<<<1, 1024>>>();
    fill_kernel<<<(N_EDGES + 255) / 256, 256>>>(src, dst);

    const int tile_grid = (N_NODES + 63) / 64;            // 782
    const int agg_grid  = (N_NODES * 32 + 255) / 256;

    for (int step = 0; step < 3; step++) {
        const float* hcur = (step == 0) ? node_in : h;
        gemm1_kernel<<<tile_grid, 256>>>(hcur, b);
        agg_kernel<<<agg_grid, 256>>>();
        gru_kernel<<<tile_grid, 256, GRU_SMEM>>>(hcur, h);
    }
}

// round 5
// speedup vs baseline: 4.4198x; 1.3127x over previous
#include <cuda_runtime.h>
#include <math.h>

#define N_NODES 50000
#define N_EDGES 800000
#define D 64
#define N_CHUNKS ((N_NODES + 255) / 256)   // 196

typedef unsigned long long ull;

// ------------------------- device scratch (no allocs allowed) ---------------
// Referenced ONLY from device code (host-side use of a __device__ symbol
// passes the host shadow address, which ATS dereferences silently - R1/2 bug).
__device__ float g_wh[N_NODES * D];
__device__ float g_agg[N_NODES * D];
__device__ int   g_rowptr[N_NODES + 1];
__device__ int   g_cnt[N_NODES];
__device__ int   g_cursor[N_NODES];
__device__ int   g_srcsorted[N_EDGES];
__device__ int   g_chunksum[N_CHUNKS];
__device__ int   g_chunkoff[N_CHUNKS];
// pre-transposed weights / pre-combined biases (built once per launch)
__device__ float g_wihT[64 * 192];
__device__ float g_whhT[64 * 192];
__device__ float g_wT[64 * 64];
__device__ float g_brz[128];
__device__ float g_bni[64];
__device__ float g_bnh[64];

// ------------------------- f32x2 helpers ------------------------------------
__device__ __forceinline__ ull ffma2(ull a, ull b, ull c) {
    ull d;
    asm("fma.rn.f32x2 %0, %1, %2, %3;" : "=l"(d) : "l"(a), "l"(b), "l"(c));
    return d;
}
__device__ __forceinline__ ull pack2f(float x, float y) {
    ull r;
    asm("mov.b64 %0, {%1, %2};" : "=l"(r) : "f"(x), "f"(y));
    return r;
}
__device__ __forceinline__ float2 unpack2(ull v) {
    float2 f;
    asm("mov.b64 {%0, %1}, %2;" : "=f"(f.x), "=f"(f.y) : "l"(v));
    return f;
}
__device__ __forceinline__ float sigmoidf_(float x) {
    return 1.0f / (1.0f + __expf(-x));
}

// ------------------------- prep: transposes + biases + zero counts ----------
__global__ void prep_kernel(const float* __restrict__ W,
                            const float* __restrict__ Wih,
                            const float* __restrict__ Whh,
                            const float* __restrict__ bih,
                            const float* __restrict__ bhh) {
    int i = blockIdx.x * blockDim.x + threadIdx.x;
    if (i < N_NODES) g_cnt[i] = 0;
    if (i < 12288) {
        int k = i / 192, j = i % 192;
        g_wihT[i] = Wih[j * 64 + k];
    } else if (i < 24576) {
        int e = i - 12288; int k = e / 192, j = e % 192;
        g_whhT[e] = Whh[j * 64 + k];
    } else if (i < 28672) {
        int e = i - 24576; int k = e / 64, j = e % 64;
        g_wT[e] = W[j * 64 + k];
    } else if (i < 28800) {
        int d = i - 28672;
        g_brz[d] = bih[d] + bhh[d];
    } else if (i < 28864) {
        int d = i - 28800;
        g_bni[d] = bih[128 + d];
    } else if (i < 28928) {
        int d = i - 28864;
        g_bnh[d] = bhh[128 + d];
    }
}

// ------------------------- CSR build (parallel scan) -------------------------
__global__ void count_kernel(const int* __restrict__ dst) {
    int e = blockIdx.x * blockDim.x + threadIdx.x;
    if (e < N_EDGES) atomicAdd(&g_cnt[dst[e]], 1);
}

// phase 1: per-256-chunk sums
__global__ void chunksum_kernel() {
    __shared__ int ws[8];
    int b = blockIdx.x, t = threadIdx.x;
    int i = b * 256 + t;
    int v = (i < N_NODES) ? g_cnt[i] : 0;
    int x = v;
#pragma unroll
    for (int off = 16; off > 0; off >>= 1) x += __shfl_down_sync(0xffffffffu, x, off);
    if ((t & 31) == 0) ws[t >> 5] = x;
    __syncthreads();
    if (t < 8) {
        int s = ws[t];
#pragma unroll
        for (int off = 4; off > 0; off >>= 1) s += __shfl_down_sync(0xffu, s, off);
        if (t == 0) g_chunksum[b] = s;
    }
}

// phase 2: exclusive scan of N_CHUNKS (<=256) chunk sums, single block
__global__ void chunkscan_kernel() {
    __shared__ int ws[8];
    int t = threadIdx.x, lane = t & 31, w = t >> 5;
    int v = (t < N_CHUNKS) ? g_chunksum[t] : 0;
    int x = v;
#pragma unroll
    for (int off = 1; off < 32; off <<= 1) {
        int y = __shfl_up_sync(0xffffffffu, x, off);
        if (lane >= off) x += y;
    }
    if (lane == 31) ws[w] = x;
    __syncthreads();
    if (w == 0 && lane < 8) {
        int s = ws[lane];
        int xs = s;
#pragma unroll
        for (int off = 1; off < 8; off <<= 1) {
            int y = __shfl_up_sync(0xffu, xs, off);
            if (lane >= off) xs += y;
        }
        ws[lane] = xs - s;
    }
    __syncthreads();
    if (t < N_CHUNKS) g_chunkoff[t] = x + ws[w] - v;  // exclusive
    if (t == 0) g_rowptr[0] = 0;
}

// phase 3: per-chunk block scans -> rowptr + cursor
__global__ void rowptr_kernel() {
    __shared__ int ws[8];
    int b = blockIdx.x, t = threadIdx.x, lane = t & 31, w = t >> 5;
    int i = b * 256 + t;
    int v = (i < N_NODES) ? g_cnt[i] : 0;
    int x = v;
#pragma unroll
    for (int off = 1; off < 32; off <<= 1) {
        int y = __shfl_up_sync(0xffffffffu, x, off);
        if (lane >= off) x += y;
    }
    if (lane == 31) ws[w] = x;
    __syncthreads();
    if (w == 0 && lane < 8) {
        int s = ws[lane];
        int xs = s;
#pragma unroll
        for (int off = 1; off < 8; off <<= 1) {
            int y = __shfl_up_sync(0xffu, xs, off);
            if (lane >= off) xs += y;
        }
        ws[lane] = xs - s;
    }
    __syncthreads();
    if (i < N_NODES) {
        int incl = x + ws[w] + g_chunkoff[b];
        g_rowptr[i + 1] = incl;
        g_cursor[i]     = incl - v;
    }
}

__global__ void fill_kernel(const int* __restrict__ src, const int* __restrict__ dst) {
    int e = blockIdx.x * blockDim.x + threadIdx.x;
    if (e < N_EDGES) {
        int d = dst[e];
        int pos = atomicAdd(&g_cursor[d], 1);
        g_srcsorted[pos] = src[e];
    }
}

// ------------------------- wh = h @ W^T + b ----------------------------------
// 512 threads, 128 rows/CTA. thread = (rowslot t>>4, dimslot t&15 -> 4 dims),
// R=4 rows; row = rs + 32*i.
#define T_STRIDE 68
__global__ void __launch_bounds__(512) gemm1_kernel(
    const float* __restrict__ hin, const float* __restrict__ b) {
    extern __shared__ float sg[];
    float* wTs = sg;                  // [64][64]
    float* Xs  = wTs + 64 * 64;       // [128][T_STRIDE]
    float* sb  = Xs + 128 * T_STRIDE; // [64]

    int t = threadIdx.x;
    int row0 = blockIdx.x * 128;

    if (t < 64) sb[t] = b[t];
    for (int i = t; i < 1024; i += 512)
        ((float4*)wTs)[i] = ((const float4*)g_wT)[i];
    for (int i = t; i < 128 * 16; i += 512) {
        int r = i >> 4, c4 = i & 15;
        int g = row0 + r;
        float4 v = (g < N_NODES) ? ((const float4*)hin)[(size_t)g * 16 + c4]
                                 : make_float4(0.f, 0.f, 0.f, 0.f);
        *(float4*)&Xs[r * T_STRIDE + c4 * 4] = v;
    }
    __syncthreads();

    int ds = t & 15;
    int rs = t >> 4;       // 0..31
    int db = ds << 2;

    ull acc[4][2];
    {
        ull b0 = pack2f(sb[db], sb[db + 1]);
        ull b1 = pack2f(sb[db + 2], sb[db + 3]);
#pragma unroll
        for (int i = 0; i < 4; i++) { acc[i][0] = b0; acc[i][1] = b1; }
    }

#pragma unroll 8
    for (int k = 0; k < 64; k++) {
        const ull* wr = (const ull*)&wTs[k * 64 + db];
        ull w0 = wr[0], w1 = wr[1];
#pragma unroll
        for (int i = 0; i < 4; i++) {
            float x = Xs[(rs + 32 * i) * T_STRIDE + k];
            ull x2 = pack2f(x, x);
            acc[i][0] = ffma2(x2, w0, acc[i][0]);
            acc[i][1] = ffma2(x2, w1, acc[i][1]);
        }
    }
#pragma unroll
    for (int i = 0; i < 4; i++) {
        int g = row0 + rs + 32 * i;
        if (g < N_NODES) {
            float2 a = unpack2(acc[i][0]);
            float2 c = unpack2(acc[i][1]);
            *(float4*)&g_wh[(size_t)g * 64 + db] = make_float4(a.x, a.y, c.x, c.y);
        }
    }
}

// ------------------------- aggregation: one warp per dst node ---------------
__global__ void __launch_bounds__(256) agg_kernel() {
    int gw = (blockIdx.x * blockDim.x + threadIdx.x) >> 5;
    if (gw >= N_NODES) return;
    int lane = threadIdx.x & 31;
    int p = g_rowptr[gw];
    int e = g_rowptr[gw + 1];
    float ax = 0.0f, ay = 0.0f;
    for (; p + 2 <= e; p += 2) {
        int s0 = g_srcsorted[p];
        int s1 = g_srcsorted[p + 1];
        float2 m0 = *(const float2*)&g_wh[(size_t)s0 * 64 + lane * 2];
        float2 m1 = *(const float2*)&g_wh[(size_t)s1 * 64 + lane * 2];
        ax += m0.x; ay += m0.y;
        ax += m1.x; ay += m1.y;
    }
    if (p < e) {
        int s0 = g_srcsorted[p];
        float2 m0 = *(const float2*)&g_wh[(size_t)s0 * 64 + lane * 2];
        ax += m0.x; ay += m0.y;
    }
    *(float2*)&g_agg[(size_t)gw * 64 + lane * 2] = make_float2(ax, ay);
}

// ------------------------- fused GRU cell ------------------------------------
// 512 threads, 128 rows/CTA. thread = (rowslot t>>4 in 0..31, dimslot t&15 ->
// 4 dims), R=4 rows (row = rs + 32*i). Per-thread work identical to R4.
__global__ void __launch_bounds__(512) gru_kernel(
    const float* __restrict__ hin, float* __restrict__ hout) {
    extern __shared__ float sm[];
    float* WihT_s = sm;                      // [64][192]
    float* WhhT_s = WihT_s + 64 * 192;       // [64][192]
    float* As     = WhhT_s + 64 * 192;       // [128][T_STRIDE]
    float* Hs     = As + 128 * T_STRIDE;     // [128][T_STRIDE]
    float* sbrz   = Hs + 128 * T_STRIDE;     // [128]
    float* sbni   = sbrz + 128;              // [64]
    float* sbnh   = sbni + 64;               // [64]

    int t = threadIdx.x;
    int row0 = blockIdx.x * 128;

    for (int i = t; i < 3072; i += 512)
        ((float4*)WihT_s)[i] = ((const float4*)g_wihT)[i];
    for (int i = t; i < 3072; i += 512)
        ((float4*)WhhT_s)[i] = ((const float4*)g_whhT)[i];
    if (t < 128) sbrz[t] = g_brz[t];
    else if (t < 192) sbni[t - 128] = g_bni[t - 128];
    else if (t < 256) sbnh[t - 192] = g_bnh[t - 192];
    for (int i = t; i < 128 * 16; i += 512) {
        int r = i >> 4, c4 = i & 15;
        int g = row0 + r;
        float4 av = (g < N_NODES) ? *(const float4*)&g_agg[(size_t)g * 64 + c4 * 4]
                                  : make_float4(0.f, 0.f, 0.f, 0.f);
        float4 hv = (g < N_NODES) ? *(const float4*)&hin[(size_t)g * 64 + c4 * 4]
                                  : make_float4(0.f, 0.f, 0.f, 0.f);
        *(float4*)&As[r * T_STRIDE + c4 * 4] = av;
        *(float4*)&Hs[r * T_STRIDE + c4 * 4] = hv;
    }
    __syncthreads();

    int ds = t & 15;
    int rs = t >> 4;      // 0..31
    int db = ds << 2;

    ull accR[4][2], accZ[4][2], accNi[4][2], accNh[4][2];
#pragma unroll
    for (int i = 0; i < 4; i++)
#pragma unroll
        for (int p = 0; p < 2; p++) {
            accR[i][p] = 0ull; accZ[i][p] = 0ull;
            accNi[i][p] = 0ull; accNh[i][p] = 0ull;
        }

#pragma unroll 4
    for (int k = 0; k < 64; k++) {
        const ull* wiR = (const ull*)&WihT_s[k * 192 + db];
        const ull* wiZ = (const ull*)&WihT_s[k * 192 + 64 + db];
        const ull* wiN = (const ull*)&WihT_s[k * 192 + 128 + db];
        const ull* whR = (const ull*)&WhhT_s[k * 192 + db];
        const ull* whZ = (const ull*)&WhhT_s[k * 192 + 64 + db];
        const ull* whN = (const ull*)&WhhT_s[k * 192 + 128 + db];
        ull wir0 = wiR[0], wir1 = wiR[1];
        ull wiz0 = wiZ[0], wiz1 = wiZ[1];
        ull win0 = wiN[0], win1 = wiN[1];
        ull whr0 = whR[0], whr1 = whR[1];
        ull whz0 = whZ[0], whz1 = whZ[1];
        ull whn0 = whN[0], whn1 = whN[1];
#pragma unroll
        for (int i = 0; i < 4; i++) {
            int r = rs + 32 * i;
            float av = As[r * T_STRIDE + k];
            float hv = Hs[r * T_STRIDE + k];
            ull a2 = pack2f(av, av);
            ull h2 = pack2f(hv, hv);
            accR[i][0] = ffma2(a2, wir0, accR[i][0]);
            accR[i][1] = ffma2(a2, wir1, accR[i][1]);
            accR[i][0] = ffma2(h2, whr0, accR[i][0]);
            accR[i][1] = ffma2(h2, whr1, accR[i][1]);
            accZ[i][0] = ffma2(a2, wiz0, accZ[i][0]);
            accZ[i][1] = ffma2(a2, wiz1, accZ[i][1]);
            accZ[i][0] = ffma2(h2, whz0, accZ[i][0]);
            accZ[i][1] = ffma2(h2, whz1, accZ[i][1]);
            accNi[i][0] = ffma2(a2, win0, accNi[i][0]);
            accNi[i][1] = ffma2(a2, win1, accNi[i][1]);
            accNh[i][0] = ffma2(h2, whn0, accNh[i][0]);
            accNh[i][1] = ffma2(h2, whn1, accNh[i][1]);
        }
    }

#pragma unroll
    for (int i = 0; i < 4; i++) {
        int r = rs + 32 * i;
        int g = row0 + r;
        if (g >= N_NODES) continue;
        float out[4];
#pragma unroll
        for (int p = 0; p < 2; p++) {
            float2 rr = unpack2(accR[i][p]);
            float2 zz = unpack2(accZ[i][p]);
            float2 ni = unpack2(accNi[i][p]);
            float2 nh = unpack2(accNh[i][p]);
            int d = db + 2 * p;
            float r0 = sigmoidf_(rr.x + sbrz[d]);
            float r1 = sigmoidf_(rr.y + sbrz[d + 1]);
            float z0 = sigmoidf_(zz.x + sbrz[64 + d]);
            float z1 = sigmoidf_(zz.y + sbrz[64 + d + 1]);
            float n0 = tanhf(ni.x + sbni[d]     + r0 * (nh.x + sbnh[d]));
            float n1 = tanhf(ni.y + sbni[d + 1] + r1 * (nh.y + sbnh[d + 1]));
            float h0 = Hs[r * T_STRIDE + d];
            float h1 = Hs[r * T_STRIDE + d + 1];
            out[2 * p]     = (1.0f - z0) * n0 + z0 * h0;
            out[2 * p + 1] = (1.0f - z1) * n1 + z1 * h1;
        }
        *(float4*)&hout[(size_t)g * 64 + db] = make_float4(out[0], out[1], out[2], out[3]);
    }
}

// ------------------------- launch --------------------------------------------
extern "C" void kernel_launch(void* const* d_in, const int* in_sizes, int n_in,
                              void* d_out, int out_size) {
    const float *node_in = 0, *W = 0, *b = 0, *Wih = 0, *Whh = 0, *bih = 0, *bhh = 0;
    const int *src = 0, *dst = 0;
    int n12288 = 0, n192 = 0, n800k = 0;
    for (int i = 0; i < n_in; i++) {
        switch (in_sizes[i]) {
            case N_NODES * D: node_in = (const float*)d_in[i]; break;
            case D * D:       W = (const float*)d_in[i]; break;
            case D:           b = (const float*)d_in[i]; break;
            case 3 * D * D:
                if (n12288++ == 0) Wih = (const float*)d_in[i];
                else               Whh = (const float*)d_in[i];
                break;
            case 3 * D:
                if (n192++ == 0) bih = (const float*)d_in[i];
                else             bhh = (const float*)d_in[i];
                break;
            case N_EDGES:
                if (n800k++ == 0) src = (const int*)d_in[i];
                else              dst = (const int*)d_in[i];
                break;
            default: break;
        }
    }
    float* h = (float*)d_out;

    // smem: gemm1 = (4096 + 128*68 + 64)*4 = 51,456 B
    //       gru   = (2*12288 + 2*128*68 + 256)*4 = 168,960 B
    const int GEMM1_SMEM = (64 * 64 + 128 * T_STRIDE + 64) * 4;
    const int GRU_SMEM   = (2 * 12288 + 2 * 128 * T_STRIDE + 256) * 4;
    cudaFuncSetAttribute(gemm1_kernel, cudaFuncAttributeMaxDynamicSharedMemorySize, GEMM1_SMEM);
    cudaFuncSetAttribute(gru_kernel,   cudaFuncAttributeMaxDynamicSharedMemorySize, GRU_SMEM);

    // one-time prep + parallel CSR build
    prep_kernel<<<(N_NODES + 255) / 256, 256>>>(W, Wih, Whh, bih, bhh);
    count_kernel<<<(N_EDGES + 255) / 256, 256>>>(dst);
    chunksum_kernel<<<N_CHUNKS, 256>>>();
    chunkscan_kernel<<<1, 256>>>();
    rowptr_kernel<<<N_CHUNKS, 256>>>();
    fill_kernel<<<(N_EDGES + 255) / 256, 256>>>(src, dst);

    const int tile_grid = (N_NODES + 127) / 128;          // 391
    const int agg_grid  = (N_NODES * 32 + 255) / 256;

    for (int step = 0; step < 3; step++) {
        const float* hcur = (step == 0) ? node_in : h;
        gemm1_kernel<<<tile_grid, 512, GEMM1_SMEM>>>(hcur, b);
        agg_kernel<<<agg_grid, 256>>>();
        gru_kernel<<<tile_grid, 512, GRU_SMEM>>>(hcur, h);
    }
}